// round 2
// baseline (speedup 1.0000x reference)
#include <cuda_runtime.h>
#include <cstdint>
#include <math.h>

#define NN   2000
#define BB   8
#define HH   4
#define DIN  64
#define DH   128
#define BH   32      // BB*HH
#define RL   50
#define RT   40      // rows per attention block (50 tiles * 40 = 2000)
#define JT   32      // j tile
#define NJT  63      // ceil(2000/32)
#define LOG2E 1.4426950408889634f
#define LN_EPS 1e-5f

// ---------------- device scratch (static; no runtime allocation) ------------
__device__ float    g_Wh [(size_t)BH*NN*DH];     // [(bh)*N + n]*128 + o
__device__ float    g_f1 [BH*NN];
__device__ float    g_f2 [BH*NN];
__device__ float    g_m2 [BH];                   // max_j f2 per (b,h)
__device__ unsigned g_adj[NN*64];                // packed adjacency bits
__device__ int      g_hasnbr[NN];
__device__ float    g_hp [(size_t)BB*NN*HH*DH];  // h_prime, node-major [node][h][o]
__device__ float    g_enc[(size_t)BB*NN*DH];     // projected / layernormed nodes

// ---------------- helpers ---------------------------------------------------
__device__ __forceinline__ float ex2f(float x){
    float r; asm("ex2.approx.ftz.f32 %0, %1;" : "=f"(r) : "f"(x)); return r;
}
__device__ __forceinline__ unsigned long long ffma2(unsigned long long a,
                                                    unsigned long long b,
                                                    unsigned long long c){
    unsigned long long d;
    asm("fma.rn.f32x2 %0, %1, %2, %3;" : "=l"(d) : "l"(a), "l"(b), "l"(c));
    return d;
}
__device__ __forceinline__ unsigned long long packdup(float p){
    unsigned long long d;
    asm("mov.b64 %0, {%1, %2};" : "=l"(d) : "f"(p), "f"(p));
    return d;
}
__device__ __forceinline__ float u64lo(unsigned long long v){
    return __uint_as_float((unsigned)(v & 0xffffffffULL));
}
__device__ __forceinline__ float u64hi(unsigned long long v){
    return __uint_as_float((unsigned)(v >> 32));
}

// ================= K0: pack adjacency into bitmask + hasnbr =================
__global__ __launch_bounds__(256) void k_pack(const int* __restrict__ adj){
    int i = blockIdx.x;
    int t = threadIdx.x;
    int w = t >> 5, lane = t & 31;
    __shared__ unsigned orr;
    if (t == 0) orr = 0u;
    __syncthreads();
    unsigned wor = 0u;
    for (int g = w; g < 64; g += 8){
        int j = g*32 + lane;
        int v = (j < NN) ? (adj[(size_t)i*NN + j] > 0) : 0;
        unsigned word = __ballot_sync(0xffffffffu, v != 0);
        if (lane == 0){ g_adj[i*64 + g] = word; wor |= word; }
    }
    if (lane == 0 && wor) atomicOr(&orr, 1u);
    __syncthreads();
    if (t == 0) g_hasnbr[i] = (orr != 0u);
}

// ================= K1: Wh = X @ W_heads (+ f1, f2) ==========================
__global__ __launch_bounds__(256) void k_wh(const float* __restrict__ nf,
                                            const float* __restrict__ Wheads,
                                            const float* __restrict__ a1,
                                            const float* __restrict__ a2){
    __shared__ float Ws[DIN*DH];       // 32KB
    __shared__ float Xs[32][DIN+1];
    __shared__ float a1s[DH], a2s[DH];
    __shared__ float f1p[32][17], f2p[32][17];

    int bh = blockIdx.y;
    int h  = bh & 3, b = bh >> 2;
    int rowbase = blockIdx.x * 32;
    int t = threadIdx.x;

    const float* Wg = Wheads + (size_t)h*DIN*DH;
    for (int i = t; i < DIN*DH; i += 256) Ws[i] = Wg[i];
    if (t < DH){ a1s[t] = a1[h*DH+t]; a2s[t] = a2[h*DH+t]; }
    for (int i = t; i < 32*DIN; i += 256){
        int r = i >> 6, d = i & 63;
        int row = rowbase + r;
        Xs[r][d] = (row < NN) ? nf[((size_t)b*NN + row)*DIN + d] : 0.f;
    }
    __syncthreads();

    int tr = t >> 4, tc = t & 15;
    int r0 = tr*2, c0 = tc*8;
    float acc[2][8];
    #pragma unroll
    for (int r = 0; r < 2; r++)
        #pragma unroll
        for (int c = 0; c < 8; c++) acc[r][c] = 0.f;

    #pragma unroll 4
    for (int k = 0; k < DIN; k++){
        float x0 = Xs[r0][k], x1 = Xs[r0+1][k];
        float4 wA = *(const float4*)&Ws[k*DH + c0];
        float4 wB = *(const float4*)&Ws[k*DH + c0 + 4];
        acc[0][0] = fmaf(x0, wA.x, acc[0][0]); acc[0][1] = fmaf(x0, wA.y, acc[0][1]);
        acc[0][2] = fmaf(x0, wA.z, acc[0][2]); acc[0][3] = fmaf(x0, wA.w, acc[0][3]);
        acc[0][4] = fmaf(x0, wB.x, acc[0][4]); acc[0][5] = fmaf(x0, wB.y, acc[0][5]);
        acc[0][6] = fmaf(x0, wB.z, acc[0][6]); acc[0][7] = fmaf(x0, wB.w, acc[0][7]);
        acc[1][0] = fmaf(x1, wA.x, acc[1][0]); acc[1][1] = fmaf(x1, wA.y, acc[1][1]);
        acc[1][2] = fmaf(x1, wA.z, acc[1][2]); acc[1][3] = fmaf(x1, wA.w, acc[1][3]);
        acc[1][4] = fmaf(x1, wB.x, acc[1][4]); acc[1][5] = fmaf(x1, wB.y, acc[1][5]);
        acc[1][6] = fmaf(x1, wB.z, acc[1][6]); acc[1][7] = fmaf(x1, wB.w, acc[1][7]);
    }

    #pragma unroll
    for (int r = 0; r < 2; r++){
        float p1 = 0.f, p2 = 0.f;
        #pragma unroll
        for (int c = 0; c < 8; c++){
            p1 = fmaf(acc[r][c], a1s[c0+c], p1);
            p2 = fmaf(acc[r][c], a2s[c0+c], p2);
        }
        f1p[r0+r][tc] = p1;
        f2p[r0+r][tc] = p2;
        int row = rowbase + r0 + r;
        if (row < NN){
            float* dst = &g_Wh[((size_t)bh*NN + row)*DH + c0];
            *(float4*)(dst)   = make_float4(acc[r][0],acc[r][1],acc[r][2],acc[r][3]);
            *(float4*)(dst+4) = make_float4(acc[r][4],acc[r][5],acc[r][6],acc[r][7]);
        }
    }
    __syncthreads();
    if (t < 32){
        float s1 = 0.f, s2 = 0.f;
        #pragma unroll
        for (int c = 0; c < 16; c++){ s1 += f1p[t][c]; s2 += f2p[t][c]; }
        int row = rowbase + t;
        if (row < NN){ g_f1[bh*NN+row] = s1; g_f2[bh*NN+row] = s2; }
    }
}

// ================= K2: per-(b,h) global max of f2 ===========================
__global__ __launch_bounds__(256) void k_m2(){
    int bh = blockIdx.x;
    int t = threadIdx.x;
    float m = -3.0e38f;
    for (int i = t; i < NN; i += 256) m = fmaxf(m, g_f2[bh*NN + i]);
    #pragma unroll
    for (int off = 16; off; off >>= 1)
        m = fmaxf(m, __shfl_xor_sync(0xffffffffu, m, off));
    __shared__ float sm[8];
    if ((t & 31) == 0) sm[t >> 5] = m;
    __syncthreads();
    if (t == 0){
        float mm = sm[0];
        #pragma unroll
        for (int w = 1; w < 8; w++) mm = fmaxf(mm, sm[w]);
        g_m2[bh] = mm;
    }
}

// ================= K3: fused attention (score/softmax/AV) ===================
__global__ __launch_bounds__(256) void k_attn(){
    __shared__ __align__(16) float sbuf[5376];   // whs[4096] | ps[1280]; reused as red
    __shared__ float w_all_f[RT*65/1];           // placeholder sizing below
    // (real adjacency cache)
    __shared__ unsigned w_all[RT*65];            // padded 65 to avoid bank conflicts
    __shared__ float c1s[RT], c2s[RT], s_sm[RT], rs_sm[RT];
    __shared__ unsigned u_s[RT];

    float* whs = sbuf;
    float* ps  = sbuf + 4096;

    int bh = blockIdx.y;
    int b = bh >> 2, h = bh & 3;
    int rowbase = blockIdx.x * RT;
    int t = threadIdx.x;
    (void)w_all_f;

    // row setup
    if (t < RT){
        int row = rowbase + t;
        float f1  = g_f1[bh*NN + row];
        float M2  = g_m2[bh];
        float tL  = (f1 + M2)*LOG2E;
        float mL2 = fmaxf(tL, 0.2f*tL);
        c1s[t] = f1*LOG2E - mL2;
        c2s[t] = 0.2f*f1*LOG2E - mL2;
        u_s[t] = (g_hasnbr[row] == 0);
        s_sm[t] = 0.f;
    }
    // adjacency cache: 40 rows x 64 words
    for (int i = t; i < RT*64; i += 256){
        int r = i >> 6, gg = i & 63;
        w_all[r*65 + gg] = g_adj[(rowbase + r)*64 + gg];
    }
    __syncthreads();

    unsigned long long acc[RT/2];
    #pragma unroll
    for (int q = 0; q < RT/2; q++) acc[q] = 0ull;
    float s_part[5] = {0.f,0.f,0.f,0.f,0.f};

    int d = t & 127, g = t >> 7;
    const float* Whb = g_Wh + (size_t)bh*NN*DH;
    const float* f2b = g_f2 + bh*NN;

    for (int tile = 0; tile < NJT; tile++){
        int j0 = tile*JT;
        // stage Wh tile
        if (j0 + JT <= NN){
            const float4* src = (const float4*)(Whb + (size_t)j0*DH);
            float4* dst = (float4*)whs;
            #pragma unroll
            for (int k = 0; k < 4; k++) dst[t + 256*k] = src[t + 256*k];
        } else {
            #pragma unroll
            for (int k = 0; k < 16; k++){
                int idx = t + 256*k;
                int jj = j0 + (idx >> 7);
                whs[idx] = (jj < NN) ? Whb[(size_t)jj*DH + (idx & 127)] : 0.f;
            }
        }
        __syncthreads();
        // producer: p values
        #pragma unroll
        for (int ii = 0; ii < 5; ii++){
            int idx = t + 256*ii;
            int j = idx / RT;
            int r = idx - j*RT;
            int jj = j0 + j;
            float p = 0.f;
            if (jj < NN){
                float f2L = f2b[jj]*LOG2E;
                float arg = fmaxf(c1s[r] + f2L, c2s[r] + 0.2f*f2L);
                unsigned w = w_all[r*65 + tile];
                p = ((w >> j) & 1u) ? ex2f(arg) : 0.f;
                if (u_s[r]) p = 1.f;
            }
            ps[idx] = p;
            s_part[ii] += p;
        }
        __syncthreads();
        // consumer: acc += p * Wh  (packed over row pairs)
        for (int j = g; j < JT; j += 2){
            unsigned long long wd = packdup(whs[j*DH + d]);
            const ulonglong2* pr = (const ulonglong2*)(ps + j*RT);
            #pragma unroll
            for (int q = 0; q < RT/4; q++){
                ulonglong2 pv = pr[q];
                acc[2*q]   = ffma2(wd, pv.x, acc[2*q]);
                acc[2*q+1] = ffma2(wd, pv.y, acc[2*q+1]);
            }
        }
        __syncthreads();
    }

    // row-sum reduction
    #pragma unroll
    for (int ii = 0; ii < 5; ii++){
        int idx = t + 256*ii;
        int r = idx % RT;
        atomicAdd(&s_sm[r], s_part[ii]);
    }
    __syncthreads();
    if (t < RT) rs_sm[t] = 1.0f / s_sm[t];
    // cross-group reduce: group1 stores, group0 finalizes
    unsigned long long* red = (unsigned long long*)sbuf;   // 128*20*8B = 20480B
    if (g == 1){
        #pragma unroll
        for (int q = 0; q < RT/2; q++) red[d*(RT/2) + q] = acc[q];
    }
    __syncthreads();
    if (g == 0){
        #pragma unroll
        for (int q = 0; q < RT/2; q++){
            unsigned long long o = red[d*(RT/2) + q];
            float h0 = (u64lo(acc[q]) + u64lo(o)) * rs_sm[2*q];
            float h1 = (u64hi(acc[q]) + u64hi(o)) * rs_sm[2*q+1];
            int row0 = rowbase + 2*q;
            g_hp[(((size_t)b*NN + row0  )*HH + h)*DH + d] = h0;
            g_hp[(((size_t)b*NN + row0+1)*HH + h)*DH + d] = h1;
        }
    }
}

// ================= K4: x = elu(concat) @ Wp + bp ============================
__global__ __launch_bounds__(128) void k_proj(const float* __restrict__ Wp,
                                              const float* __restrict__ bp){
    __shared__ float xs[512*17];   // [k][node], padded
    int nodebase = blockIdx.x * 16;
    int t = threadIdx.x;
    // stage + elu
    for (int i = t; i < 16*512; i += 128){
        int n = i >> 9, k = i & 511;
        float v = g_hp[(size_t)(nodebase + n)*512 + k];
        float e = (v > 0.f) ? v : expm1f(v);
        xs[k*17 + n] = e;
    }
    __syncthreads();
    float accv[16];
    #pragma unroll
    for (int n = 0; n < 16; n++) accv[n] = 0.f;
    int dcol = t;   // 0..127
    #pragma unroll 2
    for (int k = 0; k < 512; k++){
        float w = Wp[k*DH + dcol];
        const float* xr = &xs[k*17];
        #pragma unroll
        for (int n = 0; n < 16; n++) accv[n] = fmaf(xr[n], w, accv[n]);
    }
    float bias = bp[dcol];
    #pragma unroll
    for (int n = 0; n < 16; n++)
        g_enc[(size_t)(nodebase + n)*DH + dcol] = accv[n] + bias;
}

// ================= K5: LayerNorm (in place on g_enc) ========================
__global__ __launch_bounds__(128) void k_ln(const float* __restrict__ gamma,
                                            const float* __restrict__ beta){
    int t = threadIdx.x;
    int node = blockIdx.x*4 + (t >> 5);
    int lane = t & 31;
    float4* p = (float4*)(g_enc + (size_t)node*DH);
    float4 v = p[lane];
    float s  = v.x + v.y + v.z + v.w;
    float sq = v.x*v.x + v.y*v.y + v.z*v.z + v.w*v.w;
    #pragma unroll
    for (int off = 16; off; off >>= 1){
        s  += __shfl_xor_sync(0xffffffffu, s, off);
        sq += __shfl_xor_sync(0xffffffffu, sq, off);
    }
    float mean = s * (1.0f/DH);
    float var  = sq * (1.0f/DH) - mean*mean;
    float rs   = rsqrtf(var + LN_EPS);
    float4 gm = ((const float4*)gamma)[lane];
    float4 bt = ((const float4*)beta)[lane];
    float4 o;
    o.x = (v.x - mean)*rs*gm.x + bt.x;
    o.y = (v.y - mean)*rs*gm.y + bt.y;
    o.z = (v.z - mean)*rs*gm.z + bt.z;
    o.w = (v.w - mean)*rs*gm.w + bt.w;
    p[lane] = o;
}

// ================= K6: route/global embedding + MLP head ====================
__global__ __launch_bounds__(256) void k_head(const int* __restrict__ routes_raw,
        const float* __restrict__ W1, const float* __restrict__ b1,
        const float* __restrict__ W2, const float* __restrict__ b2,
        const float* __restrict__ Wv1, const float* __restrict__ bv1,
        const float* __restrict__ Wv2, const float* __restrict__ bv2,
        float* __restrict__ out){
    __shared__ float ge[DH], re[DH], comb[2*DH], h1[DH], h2[64], h3[32];
    __shared__ int ridx[RL];
    __shared__ float rvalid[RL];
    __shared__ int is64_s;
    __shared__ float cnt_s;

    int b = blockIdx.x;
    int t = threadIdx.x;

    if (t == 0){
        int is64 = 1;
        for (int k = 0; k < 200; k++){          // only first 400 int32 words: safe
            int hi = routes_raw[2*k + 1];
            if (hi != 0 && hi != -1){ is64 = 0; break; }
        }
        is64_s = is64;
    }
    __syncthreads();
    if (t < RL){
        long long v;
        if (is64_s) v = ((const long long*)routes_raw)[b*RL + t];
        else        v = (long long)routes_raw[b*RL + t];
        ridx[t]   = (v < 0) ? 0 : (int)v;
        rvalid[t] = (v >= 0) ? 1.f : 0.f;
    }
    __syncthreads();

    int d = t & 127, g2 = t >> 7;
    const float* eb = g_enc + (size_t)b*NN*DH;
    float ga = 0.f;
    for (int n = g2; n < NN; n += 2) ga += eb[(size_t)n*DH + d];
    float ra = 0.f;
    for (int l = g2; l < RL; l += 2) ra += rvalid[l] * eb[(size_t)ridx[l]*DH + d];
    if (g2 == 0){ ge[d] = ga; re[d] = ra; }
    __syncthreads();
    if (g2 == 1){ ge[d] += ga; re[d] += ra; }
    if (t == 0){
        float c = 0.f;
        for (int l = 0; l < RL; l++) c += rvalid[l];
        cnt_s = c;
    }
    __syncthreads();
    if (t < DH)        comb[t] = (cnt_s > 0.f) ? re[t] / fmaxf(cnt_s, 1.f) : 0.f;
    else if (t < 2*DH) comb[t] = ge[t - DH] * (1.0f/NN);
    __syncthreads();

    if (t < DH){
        float a = b1[t];
        for (int k = 0; k < 2*DH; k++) a = fmaf(comb[k], W1[k*DH + t], a);
        h1[t] = fmaxf(a, 0.f);
    }
    __syncthreads();
    if (t < 64){
        float a = b2[t];
        for (int k = 0; k < DH; k++) a = fmaf(h1[k], W2[k*64 + t], a);
        h2[t] = fmaxf(a, 0.f);
    }
    __syncthreads();
    if (t < 32){
        float a = bv1[t];
        for (int k = 0; k < 64; k++) a = fmaf(h2[k], Wv1[k*32 + t], a);
        h3[t] = fmaxf(a, 0.f);
    }
    __syncthreads();
    if (t < 3){
        float a = bv2[t];
        for (int k = 0; k < 32; k++) a = fmaf(h3[k], Wv2[k*3 + t], a);
        out[b*3 + t] = a;
    }
}

// ================= launch ===================================================
extern "C" void kernel_launch(void* const* d_in, const int* in_sizes, int n_in,
                              void* d_out, int out_size){
    (void)in_sizes; (void)n_in; (void)out_size;
    const float* nf     = (const float*)d_in[0];
    const int*   routes = (const int*)  d_in[1];
    const int*   adj    = (const int*)  d_in[2];
    const float* Wheads = (const float*)d_in[3];
    const float* a1     = (const float*)d_in[4];
    const float* a2     = (const float*)d_in[5];
    const float* Wp     = (const float*)d_in[6];
    const float* bp     = (const float*)d_in[7];
    const float* gamma  = (const float*)d_in[8];
    const float* beta   = (const float*)d_in[9];
    const float* W1     = (const float*)d_in[10];
    const float* b1     = (const float*)d_in[11];
    const float* W2     = (const float*)d_in[12];
    const float* b2     = (const float*)d_in[13];
    const float* Wv1    = (const float*)d_in[14];
    const float* bv1    = (const float*)d_in[15];
    const float* Wv2    = (const float*)d_in[16];
    const float* bv2    = (const float*)d_in[17];
    float* out = (float*)d_out;

    k_pack<<<NN, 256>>>(adj);
    k_wh  <<<dim3(63, BH), 256>>>(nf, Wheads, a1, a2);
    k_m2  <<<BH, 256>>>();
    k_attn<<<dim3(NN/RT, BH), 256>>>();
    k_proj<<<(BB*NN)/16, 128>>>(Wp, bp);
    k_ln  <<<(BB*NN)/4, 128>>>(gamma, beta);
    k_head<<<BB, 256>>>(routes, W1, b1, W2, b2, Wv1, bv1, Wv2, bv2, out);
}

// round 4
// speedup vs baseline: 2.5051x; 2.5051x over previous
#include <cuda_runtime.h>
#include <cstdint>
#include <math.h>

#define NN   2000
#define NNP  2016      // padded j-dim for WhT
#define BB   8
#define HH   4
#define DIN  64
#define DH   128
#define BH   32        // BB*HH
#define RL   50
#define MT   128       // attention M tile (rows per CTA)
#define NMT  16        // ceil(2000/128)
#define JT   32        // attention j tile
#define NJT  63        // ceil(2000/32)
#define LOG2E 1.4426950408889634f
#define LN_EPS 1e-5f
#define WPAD 36        // Whs row pad (floats)

// ---------------- device scratch (static; zero-initialized at load) ---------
__device__ float    g_WhT[(size_t)BH*DH*NNP];    // [(bh*128+d)][j] transposed Wh (tf32-rounded)
__device__ float    g_f1 [BH*NN];
__device__ float    g_f2 [BH*NN];
__device__ float    g_m2 [BH];
__device__ unsigned g_adjT[64*2048];             // [tile][row] packed adjacency
__device__ int      g_hasnbr[NN];
__device__ float    g_hp [(size_t)BB*NN*HH*DH];  // h_prime node-major
__device__ float    g_enc[(size_t)BB*NN*DH];

// ---------------- helpers ----------------------------------------------------
__device__ __forceinline__ float ex2f(float x){
    float r; asm("ex2.approx.ftz.f32 %0, %1;" : "=f"(r) : "f"(x)); return r;
}
__device__ __forceinline__ uint32_t tf32r(float f){
    uint32_t u; asm("cvt.rna.tf32.f32 %0, %1;" : "=r"(u) : "f"(f)); return u;
}
__device__ __forceinline__ void mma_tf32(float* c, const uint32_t* a,
                                         uint32_t b0, uint32_t b1){
    asm volatile("mma.sync.aligned.m16n8k8.row.col.f32.tf32.tf32.f32 "
        "{%0,%1,%2,%3}, {%4,%5,%6,%7}, {%8,%9}, {%0,%1,%2,%3};"
        : "+f"(c[0]), "+f"(c[1]), "+f"(c[2]), "+f"(c[3])
        : "r"(a[0]), "r"(a[1]), "r"(a[2]), "r"(a[3]), "r"(b0), "r"(b1));
}

// ================= K0: pack adjacency (transposed) + hasnbr =================
__global__ __launch_bounds__(256) void k_pack(const int* __restrict__ adj){
    int i = blockIdx.x;
    int t = threadIdx.x;
    int w = t >> 5, lane = t & 31;
    __shared__ unsigned orr;
    if (t == 0) orr = 0u;
    __syncthreads();
    unsigned wor = 0u;
    for (int g = w; g < 64; g += 8){
        int j = g*32 + lane;
        int v = (j < NN) ? (adj[(size_t)i*NN + j] > 0) : 0;
        unsigned word = __ballot_sync(0xffffffffu, v != 0);
        if (lane == 0){ g_adjT[g*2048 + i] = word; wor |= word; }
    }
    if (lane == 0 && wor) atomicOr(&orr, 1u);
    __syncthreads();
    if (t == 0) g_hasnbr[i] = (orr != 0u);
}

// ================= K1: WhT = (X @ W_heads)^T (tf32)  (+ f1, f2) =============
__global__ __launch_bounds__(256) void k_wh(const float* __restrict__ nf,
                                            const float* __restrict__ Wheads,
                                            const float* __restrict__ a1,
                                            const float* __restrict__ a2){
    __shared__ float Ws[DIN*DH];       // 32KB; reused as transpose buffer
    __shared__ float Xs[32][DIN+1];
    __shared__ float a1s[DH], a2s[DH];
    __shared__ float f1p[32][17], f2p[32][17];

    int bh = blockIdx.y;
    int h  = bh & 3, b = bh >> 2;
    int rowbase = blockIdx.x * 32;
    int t = threadIdx.x;

    const float* Wg = Wheads + (size_t)h*DIN*DH;
    for (int i = t; i < DIN*DH; i += 256) Ws[i] = Wg[i];
    if (t < DH){ a1s[t] = a1[h*DH+t]; a2s[t] = a2[h*DH+t]; }
    for (int i = t; i < 32*DIN; i += 256){
        int r = i >> 6, d = i & 63;
        int row = rowbase + r;
        Xs[r][d] = (row < NN) ? nf[((size_t)b*NN + row)*DIN + d] : 0.f;
    }
    __syncthreads();

    int tr = t >> 4, tc = t & 15;
    int r0 = tr*2, c0 = tc*8;
    float acc[2][8];
    #pragma unroll
    for (int r = 0; r < 2; r++)
        #pragma unroll
        for (int c = 0; c < 8; c++) acc[r][c] = 0.f;

    #pragma unroll 4
    for (int k = 0; k < DIN; k++){
        float x0 = Xs[r0][k], x1 = Xs[r0+1][k];
        float4 wA = *(const float4*)&Ws[k*DH + c0];
        float4 wB = *(const float4*)&Ws[k*DH + c0 + 4];
        acc[0][0] = fmaf(x0, wA.x, acc[0][0]); acc[0][1] = fmaf(x0, wA.y, acc[0][1]);
        acc[0][2] = fmaf(x0, wA.z, acc[0][2]); acc[0][3] = fmaf(x0, wA.w, acc[0][3]);
        acc[0][4] = fmaf(x0, wB.x, acc[0][4]); acc[0][5] = fmaf(x0, wB.y, acc[0][5]);
        acc[0][6] = fmaf(x0, wB.z, acc[0][6]); acc[0][7] = fmaf(x0, wB.w, acc[0][7]);
        acc[1][0] = fmaf(x1, wA.x, acc[1][0]); acc[1][1] = fmaf(x1, wA.y, acc[1][1]);
        acc[1][2] = fmaf(x1, wA.z, acc[1][2]); acc[1][3] = fmaf(x1, wA.w, acc[1][3]);
        acc[1][4] = fmaf(x1, wB.x, acc[1][4]); acc[1][5] = fmaf(x1, wB.y, acc[1][5]);
        acc[1][6] = fmaf(x1, wB.z, acc[1][6]); acc[1][7] = fmaf(x1, wB.w, acc[1][7]);
    }

    // f1/f2 partials (full precision)
    #pragma unroll
    for (int r = 0; r < 2; r++){
        float p1 = 0.f, p2 = 0.f;
        #pragma unroll
        for (int c = 0; c < 8; c++){
            p1 = fmaf(acc[r][c], a1s[c0+c], p1);
            p2 = fmaf(acc[r][c], a2s[c0+c], p2);
        }
        f1p[r0+r][tc] = p1;
        f2p[r0+r][tc] = p2;
    }
    __syncthreads();
    if (t < 32){
        float s1 = 0.f, s2 = 0.f;
        #pragma unroll
        for (int c = 0; c < 16; c++){ s1 += f1p[t][c]; s2 += f2p[t][c]; }
        int row = rowbase + t;
        if (row < NN){ g_f1[bh*NN+row] = s1; g_f2[bh*NN+row] = s2; }
    }
    // transpose through Ws (tf32-rounded); mainloop reads of Ws done (sync above)
    float* Ts = Ws;   // [d][r] padded: d*33 + r
    #pragma unroll
    for (int r = 0; r < 2; r++)
        #pragma unroll
        for (int c = 0; c < 8; c++)
            Ts[(c0+c)*33 + (r0+r)] = __uint_as_float(tf32r(acc[r][c]));
    __syncthreads();
    {
        int d = t >> 1, half = t & 1;
        int colbase = rowbase + half*16;
        const float* src = &Ts[d*33 + half*16];
        float* dst = &g_WhT[((size_t)bh*DH + d)*NNP + colbase];
        if (colbase + 16 <= NN){
            #pragma unroll
            for (int q = 0; q < 4; q++)
                *(float4*)(dst + q*4) = make_float4(src[q*4],src[q*4+1],src[q*4+2],src[q*4+3]);
        } else {
            for (int i = 0; i < 16; i++)
                if (colbase + i < NN) dst[i] = src[i];
        }
    }
}

// ================= K2: per-(b,h) global max of f2 ===========================
__global__ __launch_bounds__(256) void k_m2(){
    int bh = blockIdx.x;
    int t = threadIdx.x;
    float m = -3.0e38f;
    for (int i = t; i < NN; i += 256) m = fmaxf(m, g_f2[bh*NN + i]);
    #pragma unroll
    for (int off = 16; off; off >>= 1)
        m = fmaxf(m, __shfl_xor_sync(0xffffffffu, m, off));
    __shared__ float sm[8];
    if ((t & 31) == 0) sm[t >> 5] = m;
    __syncthreads();
    if (t == 0){
        float mm = sm[0];
        #pragma unroll
        for (int w = 1; w < 8; w++) mm = fmaxf(mm, sm[w]);
        g_m2[bh] = mm;
    }
}

// ================= K3: fused attention via mma.sync tf32 ====================
// Warp w owns rows [w*16, w*16+16); lane l: rows lr0 = w*16 + (l>>2), lr1 = lr0+8.
// A(P) fragments computed directly in registers; B(WhT) staged in smem.
__global__ __launch_bounds__(256) void k_attn(){
    __shared__ float f2a[NNP];         // f2 * log2e, padded with 0
    __shared__ float Whs[DH*WPAD];     // tile: [d][j_local], pad 36

    int bh = blockIdx.y;
    int b = bh >> 2, h = bh & 3;
    int rowbase = blockIdx.x * MT;
    int t = threadIdx.x, w = t >> 5, l = t & 31;
    int jc = l & 3;

    const float* f2b = g_f2 + bh*NN;
    for (int i = t; i < NNP; i += 256)
        f2a[i] = (i < NN) ? f2b[i]*LOG2E : 0.f;

    // per-lane row constants
    int lr0 = w*16 + (l >> 2);
    int gr0 = rowbase + lr0, gr1 = gr0 + 8;
    bool v0 = gr0 < NN, v1 = gr1 < NN;
    float M2 = g_m2[bh];
    float c1_0 = 0.f, c2_0 = 0.f, c1_1 = 0.f, c2_1 = 0.f;
    int uf0 = 0, uf1 = 0;
    if (v0){
        float f1 = g_f1[bh*NN + gr0];
        float tL = (f1 + M2)*LOG2E, mL = fmaxf(tL, 0.2f*tL);
        c1_0 = f1*LOG2E - mL; c2_0 = 0.2f*f1*LOG2E - mL;
        uf0 = (g_hasnbr[gr0] == 0);
    }
    if (v1){
        float f1 = g_f1[bh*NN + gr1];
        float tL = (f1 + M2)*LOG2E, mL = fmaxf(tL, 0.2f*tL);
        c1_1 = f1*LOG2E - mL; c2_1 = 0.2f*f1*LOG2E - mL;
        uf1 = (g_hasnbr[gr1] == 0);
    }

    float acc[16][4];
    #pragma unroll
    for (int nf = 0; nf < 16; nf++)
        #pragma unroll
        for (int q = 0; q < 4; q++) acc[nf][q] = 0.f;
    float s0 = 0.f, s1 = 0.f;

    __syncthreads();   // f2a ready

    const float* WhTb = g_WhT + (size_t)bh*DH*NNP;

    for (int tile = 0; tile < NJT; tile++){
        int j0 = tile*JT;

        // issue staging LDGs early (B tile: 128 d x 32 j)
        float4 stg[4];
        {
            int dq = t >> 3, jq = t & 7;
            #pragma unroll
            for (int it = 0; it < 4; it++)
                stg[it] = *(const float4*)&WhTb[(size_t)(dq + 32*it)*NNP + j0 + jq*4];
        }

        // A fragments (P) in mma layout
        unsigned aw0 = v0 ? g_adjT[tile*2048 + gr0] : 0u;
        unsigned aw1 = v1 ? g_adjT[tile*2048 + gr1] : 0u;
        uint32_t afr[4][4];
        #pragma unroll
        for (int ks = 0; ks < 4; ks++){
            int ja = 8*ks + jc, jb = ja + 4;
            float fa = f2a[j0 + ja], fb = f2a[j0 + jb];
            // row lr0
            float p00 = ((aw0 >> ja) & 1u) ? ex2f(fmaxf(c1_0 + fa, c2_0 + 0.2f*fa)) : 0.f;
            float p02 = ((aw0 >> jb) & 1u) ? ex2f(fmaxf(c1_0 + fb, c2_0 + 0.2f*fb)) : 0.f;
            if (uf0){ p00 = (j0 + ja < NN) ? 1.f : 0.f; p02 = (j0 + jb < NN) ? 1.f : 0.f; }
            // row lr1
            float p01 = ((aw1 >> ja) & 1u) ? ex2f(fmaxf(c1_1 + fa, c2_1 + 0.2f*fa)) : 0.f;
            float p03 = ((aw1 >> jb) & 1u) ? ex2f(fmaxf(c1_1 + fb, c2_1 + 0.2f*fb)) : 0.f;
            if (uf1){ p01 = (j0 + ja < NN) ? 1.f : 0.f; p03 = (j0 + jb < NN) ? 1.f : 0.f; }
            uint32_t u0 = tf32r(p00), u1 = tf32r(p01), u2 = tf32r(p02), u3 = tf32r(p03);
            afr[ks][0] = u0; afr[ks][1] = u1; afr[ks][2] = u2; afr[ks][3] = u3;
            s0 += __uint_as_float(u0) + __uint_as_float(u2);
            s1 += __uint_as_float(u1) + __uint_as_float(u3);
        }

        __syncthreads();   // previous tile's B reads finished
        {
            int dq = t >> 3, jq = t & 7;
            #pragma unroll
            for (int it = 0; it < 4; it++)
                *(float4*)&Whs[(dq + 32*it)*WPAD + jq*4] = stg[it];
        }
        __syncthreads();   // B tile visible

        // MMA: 16 n-frags x 4 k-steps
        int brow = l >> 2;   // d offset within n-frag
        #pragma unroll
        for (int ks = 0; ks < 4; ks++){
            #pragma unroll
            for (int nf = 0; nf < 16; nf++){
                const float* bp = &Whs[(8*nf + brow)*WPAD + 8*ks + jc];
                uint32_t b0 = __float_as_uint(bp[0]);
                uint32_t b1 = __float_as_uint(bp[4]);
                mma_tf32(acc[nf], afr[ks], b0, b1);
            }
        }
    }

    // rowsum reduce within quad (lanes sharing a row)
    s0 += __shfl_xor_sync(0xffffffffu, s0, 1);
    s0 += __shfl_xor_sync(0xffffffffu, s0, 2);
    s1 += __shfl_xor_sync(0xffffffffu, s1, 1);
    s1 += __shfl_xor_sync(0xffffffffu, s1, 2);
    float r0inv = (v0 && s0 != 0.f) ? 1.0f/s0 : 0.f;
    float r1inv = (v1 && s1 != 0.f) ? 1.0f/s1 : 0.f;

    // epilogue: scale + store
    float* hp0 = v0 ? &g_hp[(((size_t)b*NN + gr0)*HH + h)*DH] : nullptr;
    float* hp1 = v1 ? &g_hp[(((size_t)b*NN + gr1)*HH + h)*DH] : nullptr;
    #pragma unroll
    for (int nf = 0; nf < 16; nf++){
        int d0 = 8*nf + 2*jc;
        if (v0) *(float2*)(hp0 + d0) = make_float2(acc[nf][0]*r0inv, acc[nf][1]*r0inv);
        if (v1) *(float2*)(hp1 + d0) = make_float2(acc[nf][2]*r1inv, acc[nf][3]*r1inv);
    }
}

// ================= K4: x = elu(concat) @ Wp + bp ============================
__global__ __launch_bounds__(128) void k_proj(const float* __restrict__ Wp,
                                              const float* __restrict__ bp){
    __shared__ float xs[512*17];
    int nodebase = blockIdx.x * 16;
    int t = threadIdx.x;
    for (int i = t; i < 16*512; i += 128){
        int n = i >> 9, k = i & 511;
        float v = g_hp[(size_t)(nodebase + n)*512 + k];
        float e = (v > 0.f) ? v : expm1f(v);
        xs[k*17 + n] = e;
    }
    __syncthreads();
    float accv[16];
    #pragma unroll
    for (int n = 0; n < 16; n++) accv[n] = 0.f;
    int dcol = t;
    #pragma unroll 2
    for (int k = 0; k < 512; k++){
        float w = Wp[k*DH + dcol];
        const float* xr = &xs[k*17];
        #pragma unroll
        for (int n = 0; n < 16; n++) accv[n] = fmaf(xr[n], w, accv[n]);
    }
    float bias = bp[dcol];
    #pragma unroll
    for (int n = 0; n < 16; n++)
        g_enc[(size_t)(nodebase + n)*DH + dcol] = accv[n] + bias;
}

// ================= K5: LayerNorm =============================================
__global__ __launch_bounds__(128) void k_ln(const float* __restrict__ gamma,
                                            const float* __restrict__ beta){
    int t = threadIdx.x;
    int node = blockIdx.x*4 + (t >> 5);
    int lane = t & 31;
    float4* p = (float4*)(g_enc + (size_t)node*DH);
    float4 v = p[lane];
    float s  = v.x + v.y + v.z + v.w;
    float sq = v.x*v.x + v.y*v.y + v.z*v.z + v.w*v.w;
    #pragma unroll
    for (int off = 16; off; off >>= 1){
        s  += __shfl_xor_sync(0xffffffffu, s, off);
        sq += __shfl_xor_sync(0xffffffffu, sq, off);
    }
    float mean = s * (1.0f/DH);
    float var  = sq * (1.0f/DH) - mean*mean;
    float rs   = rsqrtf(var + LN_EPS);
    float4 gm = ((const float4*)gamma)[lane];
    float4 bt = ((const float4*)beta)[lane];
    float4 o;
    o.x = (v.x - mean)*rs*gm.x + bt.x;
    o.y = (v.y - mean)*rs*gm.y + bt.y;
    o.z = (v.z - mean)*rs*gm.z + bt.z;
    o.w = (v.w - mean)*rs*gm.w + bt.w;
    p[lane] = o;
}

// ================= K6: route/global embedding + MLP head ====================
__global__ __launch_bounds__(256) void k_head(const int* __restrict__ routes_raw,
        const float* __restrict__ W1, const float* __restrict__ b1,
        const float* __restrict__ W2, const float* __restrict__ b2,
        const float* __restrict__ Wv1, const float* __restrict__ bv1,
        const float* __restrict__ Wv2, const float* __restrict__ bv2,
        float* __restrict__ out){
    __shared__ float ge[DH], re[DH], comb[2*DH], h1[DH], h2[64], h3[32];
    __shared__ int ridx[RL];
    __shared__ float rvalid[RL];
    __shared__ int is64_s;
    __shared__ float cnt_s;

    int b = blockIdx.x;
    int t = threadIdx.x;

    if (t == 0){
        int is64 = 1;
        for (int k = 0; k < 200; k++){
            int hi = routes_raw[2*k + 1];
            if (hi != 0 && hi != -1){ is64 = 0; break; }
        }
        is64_s = is64;
    }
    __syncthreads();
    if (t < RL){
        long long v;
        if (is64_s) v = ((const long long*)routes_raw)[b*RL + t];
        else        v = (long long)routes_raw[b*RL + t];
        ridx[t]   = (v < 0) ? 0 : (int)v;
        rvalid[t] = (v >= 0) ? 1.f : 0.f;
    }
    __syncthreads();

    int d = t & 127, g2 = t >> 7;
    const float* eb = g_enc + (size_t)b*NN*DH;
    float ga = 0.f;
    for (int n = g2; n < NN; n += 2) ga += eb[(size_t)n*DH + d];
    float ra = 0.f;
    for (int l = g2; l < RL; l += 2) ra += rvalid[l] * eb[(size_t)ridx[l]*DH + d];
    if (g2 == 0){ ge[d] = ga; re[d] = ra; }
    __syncthreads();
    if (g2 == 1){ ge[d] += ga; re[d] += ra; }
    if (t == 0){
        float c = 0.f;
        for (int l = 0; l < RL; l++) c += rvalid[l];
        cnt_s = c;
    }
    __syncthreads();
    if (t < DH)        comb[t] = (cnt_s > 0.f) ? re[t] / fmaxf(cnt_s, 1.f) : 0.f;
    else if (t < 2*DH) comb[t] = ge[t - DH] * (1.0f/NN);
    __syncthreads();

    if (t < DH){
        float a = b1[t];
        for (int k = 0; k < 2*DH; k++) a = fmaf(comb[k], W1[k*DH + t], a);
        h1[t] = fmaxf(a, 0.f);
    }
    __syncthreads();
    if (t < 64){
        float a = b2[t];
        for (int k = 0; k < DH; k++) a = fmaf(h1[k], W2[k*64 + t], a);
        h2[t] = fmaxf(a, 0.f);
    }
    __syncthreads();
    if (t < 32){
        float a = bv1[t];
        for (int k = 0; k < 64; k++) a = fmaf(h2[k], Wv1[k*32 + t], a);
        h3[t] = fmaxf(a, 0.f);
    }
    __syncthreads();
    if (t < 3){
        float a = bv2[t];
        for (int k = 0; k < 32; k++) a = fmaf(h3[k], Wv2[k*3 + t], a);
        out[b*3 + t] = a;
    }
}

// ================= launch ===================================================
extern "C" void kernel_launch(void* const* d_in, const int* in_sizes, int n_in,
                              void* d_out, int out_size){
    (void)in_sizes; (void)n_in; (void)out_size;
    const float* nf     = (const float*)d_in[0];
    const int*   routes = (const int*)  d_in[1];
    const int*   adj    = (const int*)  d_in[2];
    const float* Wheads = (const float*)d_in[3];
    const float* a1     = (const float*)d_in[4];
    const float* a2     = (const float*)d_in[5];
    const float* Wp     = (const float*)d_in[6];
    const float* bp     = (const float*)d_in[7];
    const float* gamma  = (const float*)d_in[8];
    const float* beta   = (const float*)d_in[9];
    const float* W1     = (const float*)d_in[10];
    const float* b1     = (const float*)d_in[11];
    const float* W2     = (const float*)d_in[12];
    const float* b2     = (const float*)d_in[13];
    const float* Wv1    = (const float*)d_in[14];
    const float* bv1    = (const float*)d_in[15];
    const float* Wv2    = (const float*)d_in[16];
    const float* bv2    = (const float*)d_in[17];
    float* out = (float*)d_out;

    k_pack<<<NN, 256>>>(adj);
    k_wh  <<<dim3(63, BH), 256>>>(nf, Wheads, a1, a2);
    k_m2  <<<BH, 256>>>();
    k_attn<<<dim3(NMT, BH), 256>>>();
    k_proj<<<(BB*NN)/16, 128>>>(Wp, bp);
    k_ln  <<<(BB*NN)/4, 128>>>(gamma, beta);
    k_head<<<BB, 256>>>(routes, W1, b1, W2, b2, Wv1, bv1, Wv2, bv2, out);
}

// round 5
// speedup vs baseline: 5.3379x; 2.1308x over previous
#include <cuda_runtime.h>
#include <cuda_fp16.h>
#include <cstdint>
#include <math.h>

#define NN   2000
#define NNP  2016      // padded j-dim for WhT
#define BB   8
#define HH   4
#define DIN  64
#define DH   128
#define BH   32        // BB*HH
#define RL   50
#define MT   128       // attention M tile (rows per CTA)
#define NMT  16        // ceil(2000/128)
#define JT   32        // attention j tile
#define NJT  63        // ceil(2000/32)
#define LOG2E 1.4426950408889634f
#define LN_EPS 1e-5f
#define BPAD 40        // smem tile row stride in halves (32 data + 8 pad)
#define WPK  520       // WpT row stride in halves (512 + 8 pad)

// ---------------- device scratch (static; zero-initialized at load) ---------
__device__ __half   g_WhTH[(size_t)BH*DH*NNP];   // [(bh*128+d)][j] transposed Wh, f16
__device__ float    g_f1 [BH*NN];
__device__ float    g_f2 [BH*NN];
__device__ float    g_m2 [BH];
__device__ unsigned g_adjT[64*2048];             // [tile][row] packed adjacency
__device__ int      g_hasnbr[NN];
__device__ __half   g_hpH[(size_t)BB*NN*HH*DH];  // elu(h_prime) node-major, f16
__device__ __half   g_WpTH[DH*WPK];              // WpT [n][k] f16
__device__ float    g_enc[(size_t)BB*NN*DH];
__device__ float    g_part[BB*16*DH];            // pooling partials

// ---------------- helpers ----------------------------------------------------
__device__ __forceinline__ float ex2f(float x){
    float r; asm("ex2.approx.ftz.f32 %0, %1;" : "=f"(r) : "f"(x)); return r;
}
__device__ __forceinline__ uint32_t packh2(float lo, float hi){
    __half2 h = __floats2half2_rn(lo, hi);
    return *reinterpret_cast<uint32_t*>(&h);
}
__device__ __forceinline__ void mma_f16(float* c, const uint32_t* a,
                                        uint32_t b0, uint32_t b1){
    asm volatile("mma.sync.aligned.m16n8k16.row.col.f32.f16.f16.f32 "
        "{%0,%1,%2,%3}, {%4,%5,%6,%7}, {%8,%9}, {%0,%1,%2,%3};"
        : "+f"(c[0]), "+f"(c[1]), "+f"(c[2]), "+f"(c[3])
        : "r"(a[0]), "r"(a[1]), "r"(a[2]), "r"(a[3]), "r"(b0), "r"(b1));
}

// ================= K0: pack adjacency (transposed) + hasnbr =================
__global__ __launch_bounds__(256) void k_pack(const int* __restrict__ adj){
    int i = blockIdx.x;
    int t = threadIdx.x;
    int w = t >> 5, lane = t & 31;
    __shared__ unsigned orr;
    if (t == 0) orr = 0u;
    __syncthreads();
    unsigned wor = 0u;
    for (int g = w; g < 64; g += 8){
        int j = g*32 + lane;
        int v = (j < NN) ? (adj[(size_t)i*NN + j] > 0) : 0;
        unsigned word = __ballot_sync(0xffffffffu, v != 0);
        if (lane == 0){ g_adjT[g*2048 + i] = word; wor |= word; }
    }
    if (lane == 0 && wor) atomicOr(&orr, 1u);
    __syncthreads();
    if (t == 0) g_hasnbr[i] = (orr != 0u);
}

// ================= K1: WhT = (X @ W_heads)^T (f16)  (+ f1, f2) ==============
__global__ __launch_bounds__(256) void k_wh(const float* __restrict__ nf,
                                            const float* __restrict__ Wheads,
                                            const float* __restrict__ a1,
                                            const float* __restrict__ a2){
    __shared__ float Ws[DIN*DH];       // 32KB; reused as transpose buffer
    __shared__ float Xs[32][DIN+1];
    __shared__ float a1s[DH], a2s[DH];
    __shared__ float f1p[32][17], f2p[32][17];

    int bh = blockIdx.y;
    int h  = bh & 3, b = bh >> 2;
    int rowbase = blockIdx.x * 32;
    int t = threadIdx.x;

    const float* Wg = Wheads + (size_t)h*DIN*DH;
    for (int i = t; i < DIN*DH; i += 256) Ws[i] = Wg[i];
    if (t < DH){ a1s[t] = a1[h*DH+t]; a2s[t] = a2[h*DH+t]; }
    for (int i = t; i < 32*DIN; i += 256){
        int r = i >> 6, d = i & 63;
        int row = rowbase + r;
        Xs[r][d] = (row < NN) ? nf[((size_t)b*NN + row)*DIN + d] : 0.f;
    }
    __syncthreads();

    int tr = t >> 4, tc = t & 15;
    int r0 = tr*2, c0 = tc*8;
    float acc[2][8];
    #pragma unroll
    for (int r = 0; r < 2; r++)
        #pragma unroll
        for (int c = 0; c < 8; c++) acc[r][c] = 0.f;

    #pragma unroll 4
    for (int k = 0; k < DIN; k++){
        float x0 = Xs[r0][k], x1 = Xs[r0+1][k];
        float4 wA = *(const float4*)&Ws[k*DH + c0];
        float4 wB = *(const float4*)&Ws[k*DH + c0 + 4];
        acc[0][0] = fmaf(x0, wA.x, acc[0][0]); acc[0][1] = fmaf(x0, wA.y, acc[0][1]);
        acc[0][2] = fmaf(x0, wA.z, acc[0][2]); acc[0][3] = fmaf(x0, wA.w, acc[0][3]);
        acc[0][4] = fmaf(x0, wB.x, acc[0][4]); acc[0][5] = fmaf(x0, wB.y, acc[0][5]);
        acc[0][6] = fmaf(x0, wB.z, acc[0][6]); acc[0][7] = fmaf(x0, wB.w, acc[0][7]);
        acc[1][0] = fmaf(x1, wA.x, acc[1][0]); acc[1][1] = fmaf(x1, wA.y, acc[1][1]);
        acc[1][2] = fmaf(x1, wA.z, acc[1][2]); acc[1][3] = fmaf(x1, wA.w, acc[1][3]);
        acc[1][4] = fmaf(x1, wB.x, acc[1][4]); acc[1][5] = fmaf(x1, wB.y, acc[1][5]);
        acc[1][6] = fmaf(x1, wB.z, acc[1][6]); acc[1][7] = fmaf(x1, wB.w, acc[1][7]);
    }

    // f1/f2 partials (full precision)
    #pragma unroll
    for (int r = 0; r < 2; r++){
        float p1 = 0.f, p2 = 0.f;
        #pragma unroll
        for (int c = 0; c < 8; c++){
            p1 = fmaf(acc[r][c], a1s[c0+c], p1);
            p2 = fmaf(acc[r][c], a2s[c0+c], p2);
        }
        f1p[r0+r][tc] = p1;
        f2p[r0+r][tc] = p2;
    }
    __syncthreads();
    if (t < 32){
        float s1 = 0.f, s2 = 0.f;
        #pragma unroll
        for (int c = 0; c < 16; c++){ s1 += f1p[t][c]; s2 += f2p[t][c]; }
        int row = rowbase + t;
        if (row < NN){ g_f1[bh*NN+row] = s1; g_f2[bh*NN+row] = s2; }
    }
    // transpose through Ws
    float* Ts = Ws;   // [d][r] padded: d*33 + r
    #pragma unroll
    for (int r = 0; r < 2; r++)
        #pragma unroll
        for (int c = 0; c < 8; c++)
            Ts[(c0+c)*33 + (r0+r)] = acc[r][c];
    __syncthreads();
    {
        int d = t >> 1, hf = t & 1;
        int colbase = rowbase + hf*16;
        const float* src = &Ts[d*33 + hf*16];
        __half* dst = &g_WhTH[((size_t)bh*DH + d)*NNP + colbase];
        if (colbase + 16 <= NN){
            uint32_t u[8];
            #pragma unroll
            for (int q = 0; q < 8; q++) u[q] = packh2(src[2*q], src[2*q+1]);
            uint4 o0 = make_uint4(u[0],u[1],u[2],u[3]);
            uint4 o1 = make_uint4(u[4],u[5],u[6],u[7]);
            *(uint4*)dst       = o0;
            *(uint4*)(dst + 8) = o1;
        } else {
            for (int i = 0; i < 16; i++)
                if (colbase + i < NN) dst[i] = __float2half_rn(src[i]);
        }
    }
}

// ================= K2: per-(b,h) global max of f2 ===========================
__global__ __launch_bounds__(256) void k_m2(){
    int bh = blockIdx.x;
    int t = threadIdx.x;
    float m = -3.0e38f;
    for (int i = t; i < NN; i += 256) m = fmaxf(m, g_f2[bh*NN + i]);
    #pragma unroll
    for (int off = 16; off; off >>= 1)
        m = fmaxf(m, __shfl_xor_sync(0xffffffffu, m, off));
    __shared__ float sm[8];
    if ((t & 31) == 0) sm[t >> 5] = m;
    __syncthreads();
    if (t == 0){
        float mm = sm[0];
        #pragma unroll
        for (int w = 1; w < 8; w++) mm = fmaxf(mm, sm[w]);
        g_m2[bh] = mm;
    }
}

// ================= K2b: WpT f16 conversion ==================================
__global__ __launch_bounds__(256) void k_wpcvt(const float* __restrict__ Wp){
    int id = blockIdx.x*256 + threadIdx.x;
    if (id < 512*128){
        int k = id >> 7, n = id & 127;
        g_WpTH[n*WPK + k] = __float2half_rn(Wp[id]);
    }
}

// ================= K3: fused attention via mma.sync f16 =====================
// Warp w owns rows [w*16, w*16+16); lane l: rows r=l>>2 (+8), col quad c=l&3.
// A(P) fragments computed in registers; B(WhT f16) double-buffered in smem.
__global__ __launch_bounds__(256) void k_attn(){
    __shared__ float  f2a[NNP];          // f2 * log2e
    __shared__ __half Whs[2][DH*BPAD];   // double-buffered B tile

    int bh = blockIdx.y;
    int b = bh >> 2, h = bh & 3;
    int rowbase = blockIdx.x * MT;
    int t = threadIdx.x, w = t >> 5, l = t & 31;
    int c = l & 3, r = l >> 2;

    const float* f2b = g_f2 + bh*NN;
    for (int i = t; i < NNP; i += 256)
        f2a[i] = (i < NN) ? f2b[i]*LOG2E : 0.f;

    int gr0 = rowbase + w*16 + r, gr1 = gr0 + 8;
    bool v0 = gr0 < NN, v1 = gr1 < NN;
    float M2 = g_m2[bh];
    float c1_0 = 0.f, c2_0 = 0.f, c1_1 = 0.f, c2_1 = 0.f;
    int uf0 = 0, uf1 = 0;
    if (v0){
        float f1 = g_f1[bh*NN + gr0];
        float tL = (f1 + M2)*LOG2E, mL = fmaxf(tL, 0.2f*tL);
        c1_0 = f1*LOG2E - mL; c2_0 = 0.2f*f1*LOG2E - mL;
        uf0 = (g_hasnbr[gr0] == 0);
    }
    if (v1){
        float f1 = g_f1[bh*NN + gr1];
        float tL = (f1 + M2)*LOG2E, mL = fmaxf(tL, 0.2f*tL);
        c1_1 = f1*LOG2E - mL; c2_1 = 0.2f*f1*LOG2E - mL;
        uf1 = (g_hasnbr[gr1] == 0);
    }

    float acc[16][4];
    #pragma unroll
    for (int nf = 0; nf < 16; nf++)
        #pragma unroll
        for (int q = 0; q < 4; q++) acc[nf][q] = 0.f;
    float s0 = 0.f, s1 = 0.f;

    const __half* WhTb = g_WhTH + (size_t)bh*DH*NNP;
    int dq = t >> 1, seg = t & 1;

    // prologue: stage tile 0
    {
        const uint4* src = (const uint4*)(WhTb + (size_t)dq*NNP + seg*16);
        uint4 va = src[0], vb = src[1];
        uint4* dst = (uint4*)&Whs[0][dq*BPAD + seg*16];
        dst[0] = va; dst[1] = vb;
    }
    __syncthreads();

    for (int tile = 0; tile < NJT; tile++){
        int j0 = tile*JT;
        bool more = (tile + 1 < NJT);
        uint4 stA, stB;
        if (more){
            const uint4* src = (const uint4*)(WhTb + (size_t)dq*NNP + j0 + JT + seg*16);
            stA = src[0]; stB = src[1];
        }

        // ---- A fragments (P) ----
        unsigned aw0 = v0 ? g_adjT[tile*2048 + gr0] : 0u;
        unsigned aw1 = v1 ? g_adjT[tile*2048 + gr1] : 0u;
        uint32_t afr[2][4];
        #pragma unroll
        for (int ks = 0; ks < 2; ks++){
            int j1 = 16*ks + 2*c;
            int jls[4] = {j1, j1+1, j1+8, j1+9};
            float p0[4], p1[4];
            #pragma unroll
            for (int q = 0; q < 4; q++){
                int jl = jls[q], jg = j0 + jl;
                float f2L = f2a[jg];
                float aa = fmaxf(c1_0 + f2L, c2_0 + 0.2f*f2L);
                float bb = fmaxf(c1_1 + f2L, c2_1 + 0.2f*f2L);
                float pa = ((aw0 >> jl) & 1u) ? ex2f(aa) : 0.f;
                float pb = ((aw1 >> jl) & 1u) ? ex2f(bb) : 0.f;
                if (uf0) pa = (jg < NN) ? 1.f : 0.f;
                if (uf1) pb = (jg < NN) ? 1.f : 0.f;
                p0[q] = pa; p1[q] = pb;
            }
            s0 += p0[0] + p0[1] + p0[2] + p0[3];
            s1 += p1[0] + p1[1] + p1[2] + p1[3];
            afr[ks][0] = packh2(p0[0], p0[1]);
            afr[ks][1] = packh2(p1[0], p1[1]);
            afr[ks][2] = packh2(p0[2], p0[3]);
            afr[ks][3] = packh2(p1[2], p1[3]);
        }

        // ---- MMA on current buffer ----
        const __half* buf = Whs[tile & 1];
        #pragma unroll
        for (int ks = 0; ks < 2; ks++){
            #pragma unroll
            for (int nf = 0; nf < 16; nf++){
                const __half* bp = &buf[(8*nf + r)*BPAD + 16*ks + 2*c];
                uint32_t b0 = *(const uint32_t*)bp;
                uint32_t b1 = *(const uint32_t*)(bp + 8);
                mma_f16(acc[nf], afr[ks], b0, b1);
            }
        }

        // ---- store next tile ----
        if (more){
            uint4* dst = (uint4*)&Whs[(tile+1) & 1][dq*BPAD + seg*16];
            dst[0] = stA; dst[1] = stB;
        }
        __syncthreads();
    }

    // rowsum reduce within quad
    s0 += __shfl_xor_sync(0xffffffffu, s0, 1);
    s0 += __shfl_xor_sync(0xffffffffu, s0, 2);
    s1 += __shfl_xor_sync(0xffffffffu, s1, 1);
    s1 += __shfl_xor_sync(0xffffffffu, s1, 2);
    float r0inv = (v0 && s0 != 0.f) ? 1.0f/s0 : 0.f;
    float r1inv = (v1 && s1 != 0.f) ? 1.0f/s1 : 0.f;

    // epilogue: scale + elu + f16 store (concat layout [node][h*128+d])
    __half* hp0 = v0 ? &g_hpH[(((size_t)b*NN + gr0)*HH + h)*DH] : nullptr;
    __half* hp1 = v1 ? &g_hpH[(((size_t)b*NN + gr1)*HH + h)*DH] : nullptr;
    #pragma unroll
    for (int nf = 0; nf < 16; nf++){
        int d0 = 8*nf + 2*c;
        if (v0){
            float e0 = acc[nf][0]*r0inv; e0 = (e0 > 0.f) ? e0 : expm1f(e0);
            float e1 = acc[nf][1]*r0inv; e1 = (e1 > 0.f) ? e1 : expm1f(e1);
            *(uint32_t*)(hp0 + d0) = packh2(e0, e1);
        }
        if (v1){
            float e2 = acc[nf][2]*r1inv; e2 = (e2 > 0.f) ? e2 : expm1f(e2);
            float e3 = acc[nf][3]*r1inv; e3 = (e3 > 0.f) ? e3 : expm1f(e3);
            *(uint32_t*)(hp1 + d0) = packh2(e2, e3);
        }
    }
}

// ================= K4: g_enc = elu(concat) @ Wp + bp  (f16 mma) =============
__global__ __launch_bounds__(256) void k_proj(const float* __restrict__ bp){
    __shared__ __half As[DH*BPAD];
    __shared__ __half Bs[DH*BPAD];
    int nodebase = blockIdx.x * 128;
    int t = threadIdx.x, w = t >> 5, l = t & 31;
    int c = l & 3, r = l >> 2;
    int dq = t >> 1, seg = t & 1;

    float acc[16][4];
    #pragma unroll
    for (int nf = 0; nf < 16; nf++)
        #pragma unroll
        for (int q = 0; q < 4; q++) acc[nf][q] = 0.f;

    const __half* Ab = g_hpH + (size_t)nodebase*512;

    for (int kc = 0; kc < 16; kc++){
        const uint4* sa = (const uint4*)(Ab + (size_t)dq*512 + kc*32 + seg*16);
        uint4 va0 = sa[0], va1 = sa[1];
        const uint4* sb = (const uint4*)(g_WpTH + dq*WPK + kc*32 + seg*16);
        uint4 vb0 = sb[0], vb1 = sb[1];
        __syncthreads();   // previous chunk's reads complete
        uint4* da = (uint4*)&As[dq*BPAD + seg*16];
        da[0] = va0; da[1] = va1;
        uint4* db = (uint4*)&Bs[dq*BPAD + seg*16];
        db[0] = vb0; db[1] = vb1;
        __syncthreads();

        #pragma unroll
        for (int ks = 0; ks < 2; ks++){
            uint32_t af[4];
            af[0] = *(const uint32_t*)&As[(w*16 + r    )*BPAD + 16*ks + 2*c];
            af[1] = *(const uint32_t*)&As[(w*16 + r + 8)*BPAD + 16*ks + 2*c];
            af[2] = *(const uint32_t*)&As[(w*16 + r    )*BPAD + 16*ks + 2*c + 8];
            af[3] = *(const uint32_t*)&As[(w*16 + r + 8)*BPAD + 16*ks + 2*c + 8];
            #pragma unroll
            for (int nf = 0; nf < 16; nf++){
                const __half* bpp = &Bs[(8*nf + r)*BPAD + 16*ks + 2*c];
                mma_f16(acc[nf], af, *(const uint32_t*)bpp, *(const uint32_t*)(bpp + 8));
            }
        }
    }

    int n0 = nodebase + w*16 + r, n1 = n0 + 8;
    #pragma unroll
    for (int nf = 0; nf < 16; nf++){
        int d0 = 8*nf + 2*c;
        float b0v = bp[d0], b1v = bp[d0+1];
        *(float2*)&g_enc[(size_t)n0*DH + d0] = make_float2(acc[nf][0]+b0v, acc[nf][1]+b1v);
        *(float2*)&g_enc[(size_t)n1*DH + d0] = make_float2(acc[nf][2]+b0v, acc[nf][3]+b1v);
    }
}

// ================= K5: LayerNorm =============================================
__global__ __launch_bounds__(128) void k_ln(const float* __restrict__ gamma,
                                            const float* __restrict__ beta){
    int t = threadIdx.x;
    int node = blockIdx.x*4 + (t >> 5);
    int lane = t & 31;
    float4* p = (float4*)(g_enc + (size_t)node*DH);
    float4 v = p[lane];
    float s  = v.x + v.y + v.z + v.w;
    float sq = v.x*v.x + v.y*v.y + v.z*v.z + v.w*v.w;
    #pragma unroll
    for (int off = 16; off; off >>= 1){
        s  += __shfl_xor_sync(0xffffffffu, s, off);
        sq += __shfl_xor_sync(0xffffffffu, sq, off);
    }
    float mean = s * (1.0f/DH);
    float var  = sq * (1.0f/DH) - mean*mean;
    float rs   = rsqrtf(var + LN_EPS);
    float4 gm = ((const float4*)gamma)[lane];
    float4 bt = ((const float4*)beta)[lane];
    float4 o;
    o.x = (v.x - mean)*rs*gm.x + bt.x;
    o.y = (v.y - mean)*rs*gm.y + bt.y;
    o.z = (v.z - mean)*rs*gm.z + bt.z;
    o.w = (v.w - mean)*rs*gm.w + bt.w;
    p[lane] = o;
}

// ================= K6a: pooling partials ====================================
__global__ __launch_bounds__(256) void k_pool(){
    int chunk = blockIdx.x, b = blockIdx.y;
    int t = threadIdx.x, d = t & 127, g2 = t >> 7;
    const float* eb = g_enc + (size_t)b*NN*DH;
    int n0 = chunk*125;
    float s = 0.f;
    for (int n = n0 + g2; n < n0 + 125; n += 2)
        s += eb[(size_t)n*DH + d];
    __shared__ float sh[128];
    if (g2 == 0) sh[d] = s;
    __syncthreads();
    if (g2 == 1) g_part[(b*16 + chunk)*DH + d] = sh[d] + s;
}

// ================= K6b: route emb + MLP head ================================
__global__ __launch_bounds__(256) void k_head2(const int* __restrict__ routes_raw,
        const float* __restrict__ W1, const float* __restrict__ b1,
        const float* __restrict__ W2, const float* __restrict__ b2,
        const float* __restrict__ Wv1, const float* __restrict__ bv1,
        const float* __restrict__ Wv2, const float* __restrict__ bv2,
        float* __restrict__ out){
    __shared__ float ge[DH], re[DH], comb[2*DH], h1[DH], h2[64], h3[32];
    __shared__ int ridx[RL];
    __shared__ float rvalid[RL];
    __shared__ int is64_s;
    __shared__ float cnt_s;

    int b = blockIdx.x;
    int t = threadIdx.x;

    if (t == 0){
        int is64 = 1;
        for (int k = 0; k < 200; k++){
            int hi = routes_raw[2*k + 1];
            if (hi != 0 && hi != -1){ is64 = 0; break; }
        }
        is64_s = is64;
    }
    __syncthreads();
    if (t < RL){
        long long v;
        if (is64_s) v = ((const long long*)routes_raw)[b*RL + t];
        else        v = (long long)routes_raw[b*RL + t];
        ridx[t]   = (v < 0) ? 0 : (int)v;
        rvalid[t] = (v >= 0) ? 1.f : 0.f;
    }
    __syncthreads();

    int d = t & 127, g2 = t >> 7;
    const float* eb = g_enc + (size_t)b*NN*DH;
    // global mean from partials
    float ga = 0.f;
    for (int cch = g2*8; cch < g2*8 + 8; cch++)
        ga += g_part[(b*16 + cch)*DH + d];
    // route sum
    float ra = 0.f;
    for (int lr = g2; lr < RL; lr += 2)
        ra += rvalid[lr] * eb[(size_t)ridx[lr]*DH + d];
    if (g2 == 0){ ge[d] = ga; re[d] = ra; }
    __syncthreads();
    if (g2 == 1){ ge[d] += ga; re[d] += ra; }
    if (t == 0){
        float cc = 0.f;
        for (int lr = 0; lr < RL; lr++) cc += rvalid[lr];
        cnt_s = cc;
    }
    __syncthreads();
    if (t < DH)        comb[t] = (cnt_s > 0.f) ? re[t] / fmaxf(cnt_s, 1.f) : 0.f;
    else if (t < 2*DH) comb[t] = ge[t - DH] * (1.0f/NN);
    __syncthreads();

    if (t < DH){
        float a = b1[t];
        for (int k = 0; k < 2*DH; k++) a = fmaf(comb[k], W1[k*DH + t], a);
        h1[t] = fmaxf(a, 0.f);
    }
    __syncthreads();
    if (t < 64){
        float a = b2[t];
        for (int k = 0; k < DH; k++) a = fmaf(h1[k], W2[k*64 + t], a);
        h2[t] = fmaxf(a, 0.f);
    }
    __syncthreads();
    if (t < 32){
        float a = bv1[t];
        for (int k = 0; k < 64; k++) a = fmaf(h2[k], Wv1[k*32 + t], a);
        h3[t] = fmaxf(a, 0.f);
    }
    __syncthreads();
    if (t < 3){
        float a = bv2[t];
        for (int k = 0; k < 32; k++) a = fmaf(h3[k], Wv2[k*3 + t], a);
        out[b*3 + t] = a;
    }
}

// ================= launch ===================================================
extern "C" void kernel_launch(void* const* d_in, const int* in_sizes, int n_in,
                              void* d_out, int out_size){
    (void)in_sizes; (void)n_in; (void)out_size;
    const float* nf     = (const float*)d_in[0];
    const int*   routes = (const int*)  d_in[1];
    const int*   adj    = (const int*)  d_in[2];
    const float* Wheads = (const float*)d_in[3];
    const float* a1     = (const float*)d_in[4];
    const float* a2     = (const float*)d_in[5];
    const float* Wp     = (const float*)d_in[6];
    const float* bp     = (const float*)d_in[7];
    const float* gamma  = (const float*)d_in[8];
    const float* beta   = (const float*)d_in[9];
    const float* W1     = (const float*)d_in[10];
    const float* b1     = (const float*)d_in[11];
    const float* W2     = (const float*)d_in[12];
    const float* b2     = (const float*)d_in[13];
    const float* Wv1    = (const float*)d_in[14];
    const float* bv1    = (const float*)d_in[15];
    const float* Wv2    = (const float*)d_in[16];
    const float* bv2    = (const float*)d_in[17];
    float* out = (float*)d_out;

    k_pack <<<NN, 256>>>(adj);
    k_wh   <<<dim3(63, BH), 256>>>(nf, Wheads, a1, a2);
    k_m2   <<<BH, 256>>>();
    k_wpcvt<<<256, 256>>>(Wp);
    k_attn <<<dim3(NMT, BH), 256>>>();
    k_proj <<<125, 256>>>(bp);
    k_ln   <<<(BB*NN)/4, 128>>>(gamma, beta);
    k_pool <<<dim3(16, BB), 256>>>();
    k_head2<<<BB, 256>>>(routes, W1, b1, W2, b2, Wv1, bv1, Wv2, bv2, out);
}